// round 2
// baseline (speedup 1.0000x reference)
#include <cuda_runtime.h>
#include <math_constants.h>
#include <cstdint>

// KNN_18614388261211 — farthest-(k+1) selection, drop rank 0.
// x: (8,2048,3) f32 -> BN=16384 points, k=16.
// out: [ dists (BN*16 f32 = pair values) | idx (BN*16 as f32) ]

#define BN       16384
#define KOUT     16
#define R        8                 // rows per warp
#define NW       16                // warps per block
#define NTHREADS (NW * 32)
#define NBLOCKS  (BN / (NW * R))   // 128
#define NITER    (BN / 64)         // 256: 64 candidates per warp-iteration
#define SMEM_BYTES (BN * 3 * 4)    // 192 KB SoA: xs, ys, zs

typedef unsigned long long ull;

__device__ __forceinline__ ull f2mul(ull a, ull b) {
    ull r; asm("mul.rn.f32x2 %0,%1,%2;" : "=l"(r) : "l"(a), "l"(b)); return r;
}
__device__ __forceinline__ ull f2add(ull a, ull b) {
    ull r; asm("add.rn.f32x2 %0,%1,%2;" : "=l"(r) : "l"(a), "l"(b)); return r;
}
__device__ __forceinline__ ull packdup(float v) {
    ull r; asm("mov.b64 %0,{%1,%1};" : "=l"(r) : "f"(v)); return r;
}
__device__ __forceinline__ void unpack_f(ull v, float& lo, float& hi) {
    asm("mov.b64 {%0,%1},%2;" : "=f"(lo), "=f"(hi) : "l"(v));
}
__device__ __forceinline__ void unpack_i(ull v, int& lo, int& hi) {
    asm("mov.b64 {%0,%1},%2;" : "=r"(lo), "=r"(hi) : "l"(v));
}
__device__ __forceinline__ float fneg(float v) {
    return __int_as_float(__float_as_int(v) ^ 0x80000000u);
}

__global__ __launch_bounds__(NTHREADS, 1)
void knn_kernel(const float* __restrict__ x, float* __restrict__ out) {
    extern __shared__ float smem[];
    float* __restrict__ xs = smem;
    float* __restrict__ ys = smem + BN;
    float* __restrict__ zs = smem + 2 * BN;

    // Cooperative transpose load: AoS gmem -> SoA smem
    for (int p = threadIdx.x; p < BN; p += NTHREADS) {
        xs[p] = x[3 * p + 0];
        ys[p] = x[3 * p + 1];
        zs[p] = x[3 * p + 2];
    }
    __syncthreads();

    const int lane = threadIdx.x & 31;
    const int warp = threadIdx.x >> 5;
    const int row0 = (blockIdx.x * NW + warp) * R;
    const unsigned FULL = 0xffffffffu;

    // Per-row state: dup-packed doubled coords, -sqi, -T; distributed sorted list.
    ull rx2[R], ry2[R], rz2[R], nsqi2[R], nT2[R];
    float lv[R];
    int   lj[R];

#pragma unroll
    for (int r = 0; r < R; r++) {
        const float px = xs[row0 + r], py = ys[row0 + r], pz = zs[row0 + r];
        // sqi = ((px*px + py*py) + pz*pz), left-assoc, no fma (matches R1 exactly)
        const float sqi = __fadd_rn(__fadd_rn(__fmul_rn(px, px), __fmul_rn(py, py)),
                                    __fmul_rn(pz, pz));
        // Doubling the coefficients is exact: (2a·q + 2b·q2) + 2c·q3 == 2*((a·q+b·q2)+c·q3)
        rx2[r] = packdup(__fadd_rn(px, px));
        ry2[r] = packdup(__fadd_rn(py, py));
        rz2[r] = packdup(__fadd_rn(pz, pz));
        nsqi2[r] = packdup(fneg(sqi));
        nT2[r]   = packdup(-CUDART_INF_F);
        lv[r] = CUDART_INF_F;      // lane l (0..16) holds rank-l; 17..31 sentinels
        lj[r] = 0x7fffffff;
    }

    for (int t = 0; t < NITER; t++) {
        const int jbase = t * 64;
        const int j0 = jbase + lane * 2;
        const ull qx2 = *reinterpret_cast<const ull*>(xs + j0);
        const ull qy2 = *reinterpret_cast<const ull*>(ys + j0);
        const ull qz2 = *reinterpret_cast<const ull*>(zs + j0);
        // -sqj for both candidates (packed); x - y == x + (-y) in IEEE RN
        const ull sq2  = f2add(f2add(f2mul(qx2, qx2), f2mul(qy2, qy2)),
                               f2mul(qz2, qz2));
        const ull nsq2 = sq2 ^ 0x8000000080000000ULL;

        unsigned rowmask = 0;
#pragma unroll
        for (int r = 0; r < R; r++) {
            // pv = ((2dot - sqi) - sqj);  d = pv - T  (all as packed adds)
            const ull dot2 = f2add(f2add(f2mul(rx2[r], qx2), f2mul(ry2[r], qy2)),
                                   f2mul(rz2[r], qz2));
            const ull pv2 = f2add(f2add(dot2, nsqi2[r]), nsq2);
            const ull d2  = f2add(pv2, nT2[r]);
            int dlo, dhi; unpack_i(d2, dlo, dhi);
            // (int)d <= 0  <=>  d < 0 (incl -0 tie) or d == +0 (tie). Ties are
            // resolved (or rejected) by the insertion comparator below.
            const bool q = (dlo <= 0) | (dhi <= 0);
            rowmask = q ? (rowmask | (1u << r)) : rowmask;
        }

        if (__any_sync(FULL, rowmask != 0)) {
            unsigned rmask = __reduce_or_sync(FULL, rowmask);
            while (rmask) {
                const int r = __ffs(rmask) - 1;
                rmask &= rmask - 1;
                // Recompute this row's packed values (cheap; keeps hot path lean)
                const ull dot2 = f2add(f2add(f2mul(rx2[r], qx2), f2mul(ry2[r], qy2)),
                                       f2mul(rz2[r], qz2));
                const ull pv2 = f2add(f2add(dot2, nsqi2[r]), nsq2);
                const ull d2  = f2add(pv2, nT2[r]);
                int dlo, dhi; unpack_i(d2, dlo, dhi);
                float plo, phi; unpack_f(pv2, plo, phi);
                unsigned b0 = __ballot_sync(FULL, dlo <= 0);
                unsigned b1 = __ballot_sync(FULL, dhi <= 0);
                while (b0) {
                    const int src = __ffs(b0) - 1; b0 &= b0 - 1;
                    const float nv = __shfl_sync(FULL, plo, src);
                    const int   nj = jbase + 2 * src;
                    const bool after = (lane <= 16) &&
                        ((lv[r] > nv) || (lv[r] == nv && lj[r] > nj));
                    const unsigned im = __ballot_sync(FULL, after) & 0x1ffffu;
                    const float upv = __shfl_up_sync(FULL, lv[r], 1);
                    const int   upj = __shfl_up_sync(FULL, lj[r], 1);
                    if (im) {
                        const int pos = __ffs(im) - 1;
                        if (lane <= 16) {
                            if (lane > pos)       { lv[r] = upv; lj[r] = upj; }
                            else if (lane == pos) { lv[r] = nv;  lj[r] = nj;  }
                        }
                    }
                }
                while (b1) {
                    const int src = __ffs(b1) - 1; b1 &= b1 - 1;
                    const float nv = __shfl_sync(FULL, phi, src);
                    const int   nj = jbase + 2 * src + 1;
                    const bool after = (lane <= 16) &&
                        ((lv[r] > nv) || (lv[r] == nv && lj[r] > nj));
                    const unsigned im = __ballot_sync(FULL, after) & 0x1ffffu;
                    const float upv = __shfl_up_sync(FULL, lv[r], 1);
                    const int   upj = __shfl_up_sync(FULL, lj[r], 1);
                    if (im) {
                        const int pos = __ffs(im) - 1;
                        if (lane <= 16) {
                            if (lane > pos)       { lv[r] = upv; lj[r] = upj; }
                            else if (lane == pos) { lv[r] = nv;  lj[r] = nj;  }
                        }
                    }
                }
                const float nt = __shfl_sync(FULL, lv[r], 16);
                nT2[r] = packdup(fneg(nt));
            }
        }
    }

    // Ranks 1..16 are the output (rank 0 = farthest point dropped by reference).
#pragma unroll
    for (int r = 0; r < R; r++) {
        if (lane >= 1 && lane <= 16) {
            const int row = row0 + r;
            out[(size_t)row * KOUT + (lane - 1)] = lv[r];
            out[(size_t)BN * KOUT + (size_t)row * KOUT + (lane - 1)] = (float)lj[r];
        }
    }
}

extern "C" void kernel_launch(void* const* d_in, const int* in_sizes, int n_in,
                              void* d_out, int out_size) {
    const float* x = (const float*)d_in[0];
    float* out = (float*)d_out;
    cudaFuncSetAttribute(knn_kernel, cudaFuncAttributeMaxDynamicSharedMemorySize,
                         SMEM_BYTES);
    knn_kernel<<<NBLOCKS, NTHREADS, SMEM_BYTES>>>(x, out);
}